// round 6
// baseline (speedup 1.0000x reference)
#include <cuda_runtime.h>
#include <math.h>

#define NPTS 100000
#define CH 128
#define CH2 256
#define NPLANES 64
#define FEAT_OUT 140   // C + 12

// ------------------------- scratch (__device__ globals; no allocs allowed) ---
__device__ float g_H [(size_t)NPTS * CH2];   // fc1 output [N,256]
__device__ float g_h2[(size_t)NPTS * CH];    // fc2 output [N,128]
__device__ float g_a [(size_t)NPTS * CH];    // attention activations [N,128]
__device__ float g_num[2 * NPLANES * CH];    // pool 0 = on, pool 1 = off
__device__ float g_den[2 * NPLANES * CH];
__device__ unsigned g_cmax[CH];              // encoded per-channel max of a

// ordered-uint encoding for float atomicMax
__device__ __forceinline__ unsigned encf(float f) {
    unsigned u = __float_as_uint(f);
    return (u & 0x80000000u) ? ~u : (u | 0x80000000u);
}
__device__ __forceinline__ float decf(unsigned u) {
    return __uint_as_float((u & 0x80000000u) ? (u & 0x7fffffffu) : ~u);
}

__global__ void init_kernel() {
    int t = blockIdx.x * blockDim.x + threadIdx.x;
    if (t < 2 * NPLANES * CH) { g_num[t] = 0.f; g_den[t] = 0.f; }
    if (t < CH) g_cmax[t] = encf(-3.0e38f);
}

// ------------------------- FFMA2 helpers ------------------------------------
__device__ __forceinline__ unsigned long long dupf(float x) {
    unsigned long long r;
    asm("mov.b64 %0, {%1, %1};" : "=l"(r) : "f"(x));
    return r;
}
__device__ __forceinline__ void fma2(unsigned long long& d,
                                     unsigned long long a, unsigned long long b) {
    asm("fma.rn.f32x2 %0, %1, %2, %0;" : "+l"(d) : "l"(a), "l"(b));
}
__device__ __forceinline__ void unpk(unsigned long long v, float& lo, float& hi) {
    lo = __uint_as_float((unsigned)(v & 0xffffffffull));
    hi = __uint_as_float((unsigned)(v >> 32));
}

// ------------------------- tiled SGEMM (fp32, packed f32x2 FMA) --------------
// C[M,Nn] = epilogue(A[M,K] @ B[K,Nn])
//   EPI=0: relu(acc * sc[col] + bi[col])
//   EPI=1: raw store + per-column max -> g_cmax (encoded atomicMax)
#define BM 128
#define BN 128
#define BK 16

template <int EPI>
__global__ __launch_bounds__(256, 2)
void sgemm(const float* __restrict__ A, const float* __restrict__ B,
           float* __restrict__ Cm, const float* __restrict__ sc,
           const float* __restrict__ bi, int M, int Nn, int K)
{
    __shared__ __align__(16) float As[2][BK][BM];   // transposed A tile
    __shared__ __align__(16) float Bs[2][BK][BN];
    __shared__ unsigned smax[BN];

    const int tid = threadIdx.x;
    const int rowBase = blockIdx.x * BM;
    const int nBase = blockIdx.y * BN;
    const int tr = tid >> 4, tc = tid & 15;

    // loader coordinates: 2 float4 each for A and B per K-step
    const int aRow0 = tid >> 2,  aK0 = (tid & 3) << 2;
    const int aRow1 = aRow0 + 64;
    const int bRow0 = tid >> 5,  bN0 = (tid & 31) << 2;
    const int bRow1 = bRow0 + 8;

    unsigned long long acc[4][8];
#pragma unroll
    for (int ip = 0; ip < 4; ip++)
#pragma unroll
        for (int j = 0; j < 8; j++) acc[ip][j] = 0ull;

    const float4 z4 = make_float4(0.f, 0.f, 0.f, 0.f);

    // ---- load tile 0
    {
        float4 la0 = z4, la1 = z4;
        if (rowBase + aRow0 < M) la0 = *(const float4*)&A[(size_t)(rowBase + aRow0) * K + aK0];
        if (rowBase + aRow1 < M) la1 = *(const float4*)&A[(size_t)(rowBase + aRow1) * K + aK0];
        float4 lb0 = *(const float4*)&B[(size_t)bRow0 * Nn + nBase + bN0];
        float4 lb1 = *(const float4*)&B[(size_t)bRow1 * Nn + nBase + bN0];
        As[0][aK0 + 0][aRow0] = la0.x; As[0][aK0 + 1][aRow0] = la0.y;
        As[0][aK0 + 2][aRow0] = la0.z; As[0][aK0 + 3][aRow0] = la0.w;
        As[0][aK0 + 0][aRow1] = la1.x; As[0][aK0 + 1][aRow1] = la1.y;
        As[0][aK0 + 2][aRow1] = la1.z; As[0][aK0 + 3][aRow1] = la1.w;
        *(float4*)&Bs[0][bRow0][bN0] = lb0;
        *(float4*)&Bs[0][bRow1][bN0] = lb1;
    }
    __syncthreads();

    const int T = K / BK;
    int buf = 0;
    for (int t = 0; t < T; t++) {
        float4 la0, la1, lb0, lb1;
        const bool pf = (t + 1 < T);
        if (pf) {
            int kB = (t + 1) * BK;
            la0 = (rowBase + aRow0 < M) ? *(const float4*)&A[(size_t)(rowBase + aRow0) * K + kB + aK0] : z4;
            la1 = (rowBase + aRow1 < M) ? *(const float4*)&A[(size_t)(rowBase + aRow1) * K + kB + aK0] : z4;
            lb0 = *(const float4*)&B[(size_t)(kB + bRow0) * Nn + nBase + bN0];
            lb1 = *(const float4*)&B[(size_t)(kB + bRow1) * Nn + nBase + bN0];
        }
#pragma unroll
        for (int kk = 0; kk < BK; kk++) {
            ulonglong2 a01 = *(const ulonglong2*)&As[buf][kk][tr << 2];
            ulonglong2 a23 = *(const ulonglong2*)&As[buf][kk][64 + (tr << 2)];
            float4 b0 = *(const float4*)&Bs[buf][kk][tc << 2];
            float4 b1 = *(const float4*)&Bs[buf][kk][64 + (tc << 2)];
            unsigned long long Ar[4] = { a01.x, a01.y, a23.x, a23.y };
            float bf[8] = { b0.x, b0.y, b0.z, b0.w, b1.x, b1.y, b1.z, b1.w };
#pragma unroll
            for (int j = 0; j < 8; j++) {
                unsigned long long bb = dupf(bf[j]);
#pragma unroll
                for (int ip = 0; ip < 4; ip++) fma2(acc[ip][j], Ar[ip], bb);
            }
        }
        if (pf) {
            int nb = buf ^ 1;
            As[nb][aK0 + 0][aRow0] = la0.x; As[nb][aK0 + 1][aRow0] = la0.y;
            As[nb][aK0 + 2][aRow0] = la0.z; As[nb][aK0 + 3][aRow0] = la0.w;
            As[nb][aK0 + 0][aRow1] = la1.x; As[nb][aK0 + 1][aRow1] = la1.y;
            As[nb][aK0 + 2][aRow1] = la1.z; As[nb][aK0 + 3][aRow1] = la1.w;
            *(float4*)&Bs[nb][bRow0][bN0] = lb0;
            *(float4*)&Bs[nb][bRow1][bN0] = lb1;
        }
        __syncthreads();
        buf ^= 1;
    }

    // ---- epilogue
    float svals[8], bvals[8];
    if (EPI == 0) {
#pragma unroll
        for (int j = 0; j < 8; j++) {
            int gc = nBase + ((j < 4) ? (tc * 4 + j) : (64 + tc * 4 + j - 4));
            svals[j] = __ldg(&sc[gc]);
            bvals[j] = __ldg(&bi[gc]);
        }
    }
    if (EPI == 1) {
        if (tid < BN) smax[tid] = 0u;
        __syncthreads();
    }

    float colmx[8];
#pragma unroll
    for (int j = 0; j < 8; j++) colmx[j] = -3.0e38f;
    bool anyrow = false;

#pragma unroll
    for (int ip = 0; ip < 4; ip++) {
        int rbase = (ip < 2) ? (tr * 4 + 2 * ip) : (64 + tr * 4 + 2 * (ip - 2));
#pragma unroll
        for (int h = 0; h < 2; h++) {
            int gr = rowBase + rbase + h;
            if (gr >= M) continue;
            float o[8];
#pragma unroll
            for (int j = 0; j < 8; j++) {
                float lo, hi;
                unpk(acc[ip][j], lo, hi);
                float v = h ? hi : lo;
                if (EPI == 0) v = fmaxf(v * svals[j] + bvals[j], 0.f);
                else { colmx[j] = fmaxf(colmx[j], v); anyrow = true; }
                o[j] = v;
            }
            *(float4*)&Cm[(size_t)gr * Nn + nBase + tc * 4]      = make_float4(o[0], o[1], o[2], o[3]);
            *(float4*)&Cm[(size_t)gr * Nn + nBase + 64 + tc * 4] = make_float4(o[4], o[5], o[6], o[7]);
        }
    }

    if (EPI == 1) {
        if (anyrow) {
#pragma unroll
            for (int j = 0; j < 8; j++) {
                int lc = (j < 4) ? (tc * 4 + j) : (64 + tc * 4 + j - 4);
                atomicMax(&smax[lc], encf(colmx[j]));
            }
        }
        __syncthreads();
        if (tid < BN) atomicMax(&g_cmax[nBase + tid], smax[tid]);
    }
}

// ------------------------- fc3 logits: one warp per point --------------------
__global__ void logit_kernel(const float* __restrict__ W3, const float* __restrict__ b3,
                             float* __restrict__ out)
{
    int gw = (blockIdx.x * blockDim.x + threadIdx.x) >> 5;
    int lane = threadIdx.x & 31;
    if (gw >= NPTS) return;
    const float* row = g_h2 + (size_t)gw * CH;
    float s = 0.f;
#pragma unroll
    for (int i = 0; i < 4; i++) {
        int c = lane + 32 * i;
        s += row[c] * __ldg(&W3[c]);
    }
#pragma unroll
    for (int o = 16; o; o >>= 1) s += __shfl_xor_sync(0xffffffffu, s, o);
    if (lane == 0) out[gw] = s + __ldg(&b3[0]);
}

// ------------------------- sparse mask + attention accumulation --------------
__global__ void mask_accum(const float* __restrict__ xyz,
                           const float* __restrict__ center, const float* __restrict__ normal,
                           const float* __restrict__ pmin, const float* __restrict__ pmax,
                           const float* __restrict__ logit)
{
    __shared__ float4 sn[NPLANES];   // nx, ny, nz, offs
    __shared__ float4 sb[NPLANES];   // minx, miny, maxx, maxy
    __shared__ float scm[CH];
    int tid = threadIdx.x;
    if (tid < NPLANES) {
        float nx = normal[tid * 3], ny = normal[tid * 3 + 1], nz = normal[tid * 3 + 2];
        float off = nx * center[tid * 3] + ny * center[tid * 3 + 1] + nz * center[tid * 3 + 2];
        sn[tid] = make_float4(nx, ny, nz, off);
        sb[tid] = make_float4(pmin[tid * 3], pmin[tid * 3 + 1], pmax[tid * 3], pmax[tid * 3 + 1]);
    }
    if (tid < CH) scm[tid] = decf(g_cmax[tid]);
    __syncthreads();

    int n = blockIdx.x * blockDim.x + tid;
    unsigned long long m = 0ull;
    int sel = 0;
    if (n < NPTS) {
        float x = xyz[n * 3], y = xyz[n * 3 + 1], z = xyz[n * 3 + 2];
        sel = (logit[n] > 0.0f) ? 1 : 0;
        for (int p = 0; p < NPLANES; p++) {
            float4 nn = sn[p];
            float proj = x * nn.x + y * nn.y + z * nn.z;
            float4 bb = sb[p];
            bool ok = (fabsf(proj - nn.w) < 0.1f) &&
                      (x >= bb.x) && (x < bb.z) && (y >= bb.y) && (y < bb.w);
            if (ok) m |= (1ull << p);
        }
    }

    int lane = tid & 31;
    for (;;) {
        unsigned act = __ballot_sync(0xffffffffu, m != 0ull);
        if (!act) break;
        int src = __ffs(act) - 1;
        unsigned long long ms = __shfl_sync(0xffffffffu, m, src);
        int ns  = __shfl_sync(0xffffffffu, n, src);
        int sls = __shfl_sync(0xffffffffu, sel, src);
        int p = __ffsll((long long)ms) - 1;
        if (lane == src) m &= (m - 1);

        float* num = g_num + ((sls ? 0 : 1) * NPLANES + p) * CH;
        float* den = g_den + ((sls ? 0 : 1) * NPLANES + p) * CH;
        const float* ar = g_a  + (size_t)ns * CH;
        const float* hr = g_h2 + (size_t)ns * CH;
#pragma unroll
        for (int i = 0; i < 4; i++) {
            int c = lane + 32 * i;
            float e = expf(ar[c] - scm[c]);
            atomicAdd(&num[c], e * hr[c]);
            atomicAdd(&den[c], e);
        }
    }
}

// ------------------------- finalize: agg @ Wm + bm, relu, concat ori ---------
__global__ void finalize_kernel(const float* __restrict__ Wm, const float* __restrict__ bm,
                                const float* __restrict__ center, const float* __restrict__ normal,
                                const float* __restrict__ pmin, const float* __restrict__ pmax,
                                float* __restrict__ out)
{
    int bp = blockIdx.x;            // 0..127 : pool*64 + plane
    int pool = bp >> 6, p = bp & 63;
    __shared__ float agg[CH];
    int j = threadIdx.x;            // 128 threads
    int base = (pool * NPLANES + p) * CH;
    agg[j] = g_num[base + j] / (g_den[base + j] + 1e-9f);
    __syncthreads();

    float s = __ldg(&bm[j]);
#pragma unroll 8
    for (int c = 0; c < CH; c++) s += agg[c] * __ldg(&Wm[c * CH + j]);
    s = fmaxf(s, 0.f);

    float* ob = out + NPTS + (size_t)pool * NPLANES * FEAT_OUT + p * FEAT_OUT;
    ob[j] = s;
    if (j < 12) {
        float v;
        if (j < 3)      v = center[p * 3 + j];
        else if (j < 6) v = normal[p * 3 + (j - 3)];
        else if (j < 9) v = pmin[p * 3 + (j - 6)];
        else            v = pmax[p * 3 + (j - 9)];
        ob[CH + j] = v;
    }
}

// ------------------------- launch -------------------------------------------
extern "C" void kernel_launch(void* const* d_in, const int* in_sizes, int n_in,
                              void* d_out, int out_size)
{
    const float* feature = (const float*)d_in[0];
    const float* xyz     = (const float*)d_in[1];
    const float* center  = (const float*)d_in[2];
    const float* normal  = (const float*)d_in[3];
    const float* pmin    = (const float*)d_in[4];
    const float* pmax    = (const float*)d_in[5];
    const float* W1      = (const float*)d_in[6];
    const float* s1      = (const float*)d_in[7];
    const float* b1      = (const float*)d_in[8];
    const float* W2      = (const float*)d_in[9];
    const float* s2      = (const float*)d_in[10];
    const float* b2      = (const float*)d_in[11];
    const float* W3      = (const float*)d_in[12];
    const float* b3      = (const float*)d_in[13];
    const float* Wa      = (const float*)d_in[14];
    const float* Wm      = (const float*)d_in[15];
    const float* bm      = (const float*)d_in[16];
    float* out = (float*)d_out;

    float *Hp, *h2p, *ap;
    cudaGetSymbolAddress((void**)&Hp,  g_H);
    cudaGetSymbolAddress((void**)&h2p, g_h2);
    cudaGetSymbolAddress((void**)&ap,  g_a);

    const int MB = (NPTS + BM - 1) / BM;   // 782

    init_kernel<<<64, 256>>>();
    // fc1: H = relu((F @ W1) * s1 + b1)   [N,256]
    sgemm<0><<<dim3(MB, 2), 256>>>(feature, W1, Hp, s1, b1, NPTS, CH2, CH);
    // fc2: h2 = relu((H @ W2) * s2 + b2)  [N,128]
    sgemm<0><<<dim3(MB, 1), 256>>>(Hp, W2, h2p, s2, b2, NPTS, CH, CH2);
    // att: a = h2 @ Wa  (raw) + per-channel column max
    sgemm<1><<<dim3(MB, 1), 256>>>(h2p, Wa, ap, nullptr, nullptr, NPTS, CH, CH);
    // fc3 logits -> out[0:N)
    logit_kernel<<<(NPTS * 32 + 255) / 256, 256>>>(W3, b3, out);
    // sparse masked attention pooling accumulators
    mask_accum<<<(NPTS + 255) / 256, 256>>>(xyz, center, normal, pmin, pmax, out);
    // finalize both pools -> out[N:]
    finalize_kernel<<<128, 128>>>(Wm, bm, center, normal, pmin, pmax, out);
}